// round 4
// baseline (speedup 1.0000x reference)
#include <cuda_runtime.h>
#include <math.h>

#define BLOCK 64
#define MAXBLOCKS 256

__device__ float2 g_partials[MAXBLOCKS];
__device__ unsigned int g_count = 0;

__device__ __forceinline__ float cross2f(float ax, float ay, float bx, float by) {
    return ax * by - ay * bx;
}

// Full BEV intersection for pairs that survive the quick reject. Exactly
// replicates the JAX reference (stable compaction == stable argsort; pts[0]
// padding contributes zero area).
__device__ __noinline__ float pair_bev_inter_heavy(const float a[7], const float b[7]) {
    const float CTX[4] = {0.5f, -0.5f, -0.5f, 0.5f};
    const float CTY[4] = {0.5f, 0.5f, -0.5f, -0.5f};

    float ac = cosf(a[6]), as = sinf(a[6]);
    float bc = cosf(b[6]), bs = sinf(b[6]);

    float cax[4], cay[4], cbx[4], cby[4];
#pragma unroll
    for (int i = 0; i < 4; i++) {
        float lx = CTX[i] * a[3], ly = CTY[i] * a[4];
        cax[i] = lx * ac - ly * as + a[0];
        cay[i] = lx * as + ly * ac + a[1];
        lx = CTX[i] * b[3]; ly = CTY[i] * b[4];
        cbx[i] = lx * bc - ly * bs + b[0];
        cby[i] = lx * bs + ly * bc + b[1];
    }

    float vx[24], vy[24];
    int n = 0;
    float sx = 0.0f, sy = 0.0f;

#pragma unroll
    for (int i = 0; i < 4; i++) {
        float dx = cax[i] - b[0], dy = cay[i] - b[1];
        float qx = dx * bc + dy * bs;
        float qy = -dx * bs + dy * bc;
        if ((fabsf(qx) <= b[3] * 0.5f + 1e-5f) &&
            (fabsf(qy) <= b[4] * 0.5f + 1e-5f)) {
            vx[n] = cax[i]; vy[n] = cay[i];
            sx += cax[i]; sy += cay[i]; n++;
        }
    }
#pragma unroll
    for (int i = 0; i < 4; i++) {
        float dx = cbx[i] - a[0], dy = cby[i] - a[1];
        float qx = dx * ac + dy * as;
        float qy = -dx * as + dy * ac;
        if ((fabsf(qx) <= a[3] * 0.5f + 1e-5f) &&
            (fabsf(qy) <= a[4] * 0.5f + 1e-5f)) {
            vx[n] = cbx[i]; vy[n] = cby[i];
            sx += cbx[i]; sy += cby[i]; n++;
        }
    }
#pragma unroll
    for (int i = 0; i < 4; i++) {
        float p1x = cax[i], p1y = cay[i];
        float d1x = cax[(i + 1) & 3] - p1x, d1y = cay[(i + 1) & 3] - p1y;
#pragma unroll
        for (int j = 0; j < 4; j++) {
            float q1x = cbx[j], q1y = cby[j];
            float d2x = cbx[(j + 1) & 3] - q1x, d2y = cby[(j + 1) & 3] - q1y;
            float rx = q1x - p1x, ry = q1y - p1y;
            float den = cross2f(d1x, d1y, d2x, d2y);
            if (fabsf(den) > 1e-8f) {
                float t = cross2f(rx, ry, d2x, d2y) / den;
                float u = cross2f(rx, ry, d1x, d1y) / den;
                if ((t >= -1e-6f) && (t <= 1.0f + 1e-6f) &&
                    (u >= -1e-6f) && (u <= 1.0f + 1e-6f)) {
                    float ix = p1x + t * d1x, iy = p1y + t * d1y;
                    vx[n] = ix; vy[n] = iy;
                    sx += ix; sy += iy; n++;
                }
            }
        }
    }

    if (n < 3) return 0.0f;

    float inv = 1.0f / (float)n;
    float cenx = sx * inv, ceny = sy * inv;

    float ang[24];
    for (int k = 0; k < n; k++)
        ang[k] = atan2f(vy[k] - ceny, vx[k] - cenx);

    for (int k = 1; k < n; k++) {
        float av = ang[k], axv = vx[k], ayv = vy[k];
        int m = k - 1;
        while (m >= 0 && ang[m] > av) {
            ang[m + 1] = ang[m]; vx[m + 1] = vx[m]; vy[m + 1] = vy[m];
            m--;
        }
        ang[m + 1] = av; vx[m + 1] = axv; vy[m + 1] = ayv;
    }

    float s = 0.0f;
    for (int k = 0; k < n; k++) {
        int k2 = (k + 1 == n) ? 0 : k + 1;
        s += vx[k] * vy[k2] - vy[k] * vx[k2];
    }
    return 0.5f * fabsf(s);
}

__global__ void __launch_bounds__(BLOCK)
iou_loss_fused(const float* __restrict__ iou_pred,
               const int* __restrict__ mask,
               const int* __restrict__ ind,
               const float* __restrict__ box_pred,
               const float* __restrict__ box_gt,
               int M, int HW, int total,
               float* __restrict__ out, int out_size)
{
    int tid = blockIdx.x * BLOCK + threadIdx.x;
    float num = 0.0f, den = 0.0f;

    if (tid < total) {
        int mm = mask[tid];
        if (mm != 0) {            // masked-out pairs contribute exactly 0/0
            int b = tid / M;
            int idx = ind[tid];

            // coalesced gt load (7 floats contiguous)
            float gb[7];
            const float* gp = box_gt + (size_t)tid * 7;
#pragma unroll
            for (int d = 0; d < 7; d++) gb[d] = gp[d];

            // phase-1 scattered gather: pred + the 4 fields the reject needs
            const float* bp = box_pred + (size_t)b * 7 * HW + idx;
            float pred = iou_pred[(size_t)b * HW + idx];
            float pb0 = bp[0];
            float pb1 = bp[(size_t)1 * HW];
            float pb3 = bp[(size_t)3 * HW];
            float pb4 = bp[(size_t)4 * HW];

            // exact quick reject: separated bounding circles -> inter_bev = 0
            float dx = pb0 - gb[0], dy = pb1 - gb[1];
            float ra = 0.5f * sqrtf(pb3 * pb3 + pb4 * pb4);
            float rb = 0.5f * sqrtf(gb[3] * gb[3] + gb[4] * gb[4]);
            float rr = ra + rb + 1e-3f;

            float target;
            if (dx * dx + dy * dy > rr * rr) {
                target = -1.0f;   // iou = 0 -> 2*0-1
            } else {
                // phase-2 scattered gather for survivors only
                float pb[7];
                pb[0] = pb0; pb[1] = pb1; pb[3] = pb3; pb[4] = pb4;
                pb[2] = bp[(size_t)2 * HW];
                pb[5] = bp[(size_t)5 * HW];
                pb[6] = bp[(size_t)6 * HW];

                float inter_bev = pair_bev_inter_heavy(pb, gb);
                float top = fminf(pb[2] + pb[5] * 0.5f, gb[2] + gb[5] * 0.5f);
                float bot = fmaxf(pb[2] - pb[5] * 0.5f, gb[2] - gb[5] * 0.5f);
                float inter = inter_bev * fmaxf(top - bot, 0.0f);
                float va = pb[3] * pb[4] * pb[5];
                float vb = gb[3] * gb[4] * gb[5];
                float iou = inter / fmaxf(va + vb - inter, 1e-6f);
                target = 2.0f * iou - 1.0f;
            }

            num = fabsf(pred - target);
            den = 1.0f;
        }
    }

    // warp reduce
#pragma unroll
    for (int off = 16; off > 0; off >>= 1) {
        num += __shfl_down_sync(0xffffffffu, num, off);
        den += __shfl_down_sync(0xffffffffu, den, off);
    }
    __shared__ float2 swarp[BLOCK / 32];
    __shared__ bool s_last;
    int lane = threadIdx.x & 31, wid = threadIdx.x >> 5;
    if (lane == 0) swarp[wid] = make_float2(num, den);
    __syncthreads();

    if (threadIdx.x == 0) {
        float2 acc = swarp[0];
#pragma unroll
        for (int w = 1; w < BLOCK / 32; w++) {
            acc.x += swarp[w].x; acc.y += swarp[w].y;
        }
        g_partials[blockIdx.x] = acc;
        __threadfence();
        unsigned int v = atomicAdd(&g_count, 1u);
        s_last = (v == gridDim.x - 1);
    }
    __syncthreads();

    if (s_last) {
        float pn = 0.0f, pd = 0.0f;
        for (int i = threadIdx.x; i < (int)gridDim.x; i += BLOCK) {
            float2 p = g_partials[i];
            pn += p.x; pd += p.y;
        }
#pragma unroll
        for (int off = 16; off > 0; off >>= 1) {
            pn += __shfl_down_sync(0xffffffffu, pn, off);
            pd += __shfl_down_sync(0xffffffffu, pd, off);
        }
        if (lane == 0) swarp[wid] = make_float2(pn, pd);
        __syncthreads();
        if (threadIdx.x == 0) {
            float2 acc = swarp[0];
#pragma unroll
            for (int w = 1; w < BLOCK / 32; w++) {
                acc.x += swarp[w].x; acc.y += swarp[w].y;
            }
            float loss = acc.x / (acc.y + 1e-4f);
            for (int i = 0; i < out_size; i++) out[i] = loss;
            g_count = 0;  // reset for next graph replay
        }
    }
}

extern "C" void kernel_launch(void* const* d_in, const int* in_sizes, int n_in,
                              void* d_out, int out_size)
{
    const float* iou_pred = (const float*)d_in[0];  // (B,1,H,W)
    const int*   mask     = (const int*)d_in[1];    // (B,M)
    const int*   ind      = (const int*)d_in[2];    // (B,M)
    const float* box_pred = (const float*)d_in[3];  // (B,7,H,W)
    const float* box_gt   = (const float*)d_in[4];  // (B,M,7)

    const int B = 16;
    int BM = in_sizes[1];     // B*M
    int M = BM / B;
    int HW = in_sizes[0] / B; // C == 1

    int total = BM;
    int nblocks = (total + BLOCK - 1) / BLOCK;
    if (nblocks > MAXBLOCKS) nblocks = MAXBLOCKS;  // 8000/64 = 125

    iou_loss_fused<<<nblocks, BLOCK>>>(iou_pred, mask, ind, box_pred, box_gt,
                                       M, HW, total, (float*)d_out, out_size);
}

// round 5
// speedup vs baseline: 1.2647x; 1.2647x over previous
#include <cuda_runtime.h>
#include <math.h>

#define BLOCK 64
#define MAXBLOCKS 256

__device__ float2 g_partials[MAXBLOCKS];
__device__ unsigned int g_count = 0;

// BEV intersection area of two rotated rectangles via Sutherland–Hodgman:
// clip CCW corners of A against the 4 CCW half-planes of B. Produces the same
// convex intersection polygon as the reference's candidate+sort construction.
__device__ float bev_inter_sh(float ax, float ay, float adx, float ady, float ah,
                              float bx, float by, float bdx, float bdy, float bh)
{
    float ac, as, bc, bs;
    __sincosf(ah, &as, &ac);
    __sincosf(bh, &bs, &bc);

    const float CTX[4] = {0.5f, -0.5f, -0.5f, 0.5f};
    const float CTY[4] = {0.5f, 0.5f, -0.5f, -0.5f};

    // polygon = corners of A (CCW)
    float px[10], py[10];
#pragma unroll
    for (int i = 0; i < 4; i++) {
        float lx = CTX[i] * adx, ly = CTY[i] * ady;
        px[i] = lx * ac - ly * as + ax;
        py[i] = lx * as + ly * ac + ay;
    }
    int n = 4;

    // corners of B (CCW)
    float ex[4], ey[4];
#pragma unroll
    for (int i = 0; i < 4; i++) {
        float lx = CTX[i] * bdx, ly = CTY[i] * bdy;
        ex[i] = lx * bc - ly * bs + bx;
        ey[i] = lx * bs + ly * bc + by;
    }

    float qx[10], qy[10];
#pragma unroll
    for (int e = 0; e < 4; e++) {
        float e0x = ex[e], e0y = ey[e];
        float edx = ex[(e + 1) & 3] - e0x;
        float edy = ey[(e + 1) & 3] - e0y;

        int m = 0;
        // signed distance of each vertex to the clip line (left = inside)
        float dprev = edx * (py[n - 1] - e0y) - edy * (px[n - 1] - e0x);
        float xprev = px[n - 1], yprev = py[n - 1];
        for (int k = 0; k < n; k++) {
            float xc = px[k], yc = py[k];
            float dcur = edx * (yc - e0y) - edy * (xc - e0x);
            if ((dprev >= 0.0f) != (dcur >= 0.0f)) {
                float t = __fdividef(dprev, dprev - dcur);
                qx[m] = xprev + t * (xc - xprev);
                qy[m] = yprev + t * (yc - yprev);
                m++;
            }
            if (dcur >= 0.0f) { qx[m] = xc; qy[m] = yc; m++; }
            dprev = dcur; xprev = xc; yprev = yc;
        }
        n = m;
        if (n < 3) return 0.0f;
#pragma unroll
        for (int k = 0; k < 10; k++) { px[k] = qx[k]; py[k] = qy[k]; }
    }

    // shoelace
    float s = 0.0f;
    float x0 = px[n - 1], y0 = py[n - 1];
    for (int k = 0; k < n; k++) {
        s += x0 * py[k] - y0 * px[k];
        x0 = px[k]; y0 = py[k];
    }
    return 0.5f * fabsf(s);
}

__global__ void __launch_bounds__(BLOCK)
iou_loss_fused(const float* __restrict__ iou_pred,
               const int* __restrict__ mask,
               const int* __restrict__ ind,
               const float* __restrict__ box_pred,
               const float* __restrict__ box_gt,
               int M, int HW, int total,
               float* __restrict__ out, int out_size)
{
    int tid = blockIdx.x * BLOCK + threadIdx.x;
    float num = 0.0f, den = 0.0f;

    if (tid < total) {
        // issue ALL loads up front (independent -> max MLP, one DRAM round
        // after the ind load resolves)
        int mm = mask[tid];
        int idx = ind[tid];
        int b = tid / M;

        float gb[7];
        const float* gp = box_gt + (size_t)tid * 7;
#pragma unroll
        for (int d = 0; d < 7; d++) gb[d] = gp[d];

        const float* bp = box_pred + (size_t)b * 7 * HW + idx;
        float pred = iou_pred[(size_t)b * HW + idx];
        float pb[7];
#pragma unroll
        for (int d = 0; d < 7; d++) pb[d] = bp[(size_t)d * HW];

        if (mm != 0) {
            // exact quick reject: separated bounding circles -> inter = 0
            float dx = pb[0] - gb[0], dy = pb[1] - gb[1];
            float ra2 = pb[3] * pb[3] + pb[4] * pb[4];
            float rb2 = gb[3] * gb[3] + gb[4] * gb[4];
            float rr = 0.5f * (__fsqrt_rn(ra2) + __fsqrt_rn(rb2)) + 1e-3f;

            float target;
            if (dx * dx + dy * dy > rr * rr) {
                target = -1.0f;   // iou = 0 -> 2*0-1
            } else {
                float inter_bev = bev_inter_sh(pb[0], pb[1], pb[3], pb[4], pb[6],
                                               gb[0], gb[1], gb[3], gb[4], gb[6]);
                float top = fminf(pb[2] + pb[5] * 0.5f, gb[2] + gb[5] * 0.5f);
                float bot = fmaxf(pb[2] - pb[5] * 0.5f, gb[2] - gb[5] * 0.5f);
                float inter = inter_bev * fmaxf(top - bot, 0.0f);
                float va = pb[3] * pb[4] * pb[5];
                float vb = gb[3] * gb[4] * gb[5];
                float iou = inter / fmaxf(va + vb - inter, 1e-6f);
                target = 2.0f * iou - 1.0f;
            }

            num = fabsf(pred - target);
            den = 1.0f;
        }
    }

    // warp reduce
#pragma unroll
    for (int off = 16; off > 0; off >>= 1) {
        num += __shfl_down_sync(0xffffffffu, num, off);
        den += __shfl_down_sync(0xffffffffu, den, off);
    }
    __shared__ float2 swarp[BLOCK / 32];
    __shared__ bool s_last;
    int lane = threadIdx.x & 31, wid = threadIdx.x >> 5;
    if (lane == 0) swarp[wid] = make_float2(num, den);
    __syncthreads();

    if (threadIdx.x == 0) {
        float2 acc = swarp[0];
#pragma unroll
        for (int w = 1; w < BLOCK / 32; w++) {
            acc.x += swarp[w].x; acc.y += swarp[w].y;
        }
        g_partials[blockIdx.x] = acc;
        __threadfence();
        unsigned int v = atomicAdd(&g_count, 1u);
        s_last = (v == gridDim.x - 1);
    }
    __syncthreads();

    if (s_last) {
        float pn = 0.0f, pd = 0.0f;
        for (int i = threadIdx.x; i < (int)gridDim.x; i += BLOCK) {
            float2 p = g_partials[i];
            pn += p.x; pd += p.y;
        }
#pragma unroll
        for (int off = 16; off > 0; off >>= 1) {
            pn += __shfl_down_sync(0xffffffffu, pn, off);
            pd += __shfl_down_sync(0xffffffffu, pd, off);
        }
        if (lane == 0) swarp[wid] = make_float2(pn, pd);
        __syncthreads();
        if (threadIdx.x == 0) {
            float2 acc = swarp[0];
#pragma unroll
            for (int w = 1; w < BLOCK / 32; w++) {
                acc.x += swarp[w].x; acc.y += swarp[w].y;
            }
            float loss = acc.x / (acc.y + 1e-4f);
            for (int i = 0; i < out_size; i++) out[i] = loss;
            g_count = 0;  // reset for next graph replay
        }
    }
}

extern "C" void kernel_launch(void* const* d_in, const int* in_sizes, int n_in,
                              void* d_out, int out_size)
{
    const float* iou_pred = (const float*)d_in[0];  // (B,1,H,W)
    const int*   mask     = (const int*)d_in[1];    // (B,M)
    const int*   ind      = (const int*)d_in[2];    // (B,M)
    const float* box_pred = (const float*)d_in[3];  // (B,7,H,W)
    const float* box_gt   = (const float*)d_in[4];  // (B,M,7)

    const int B = 16;
    int BM = in_sizes[1];     // B*M
    int M = BM / B;
    int HW = in_sizes[0] / B; // C == 1

    int total = BM;
    int nblocks = (total + BLOCK - 1) / BLOCK;
    if (nblocks > MAXBLOCKS) nblocks = MAXBLOCKS;  // 8000/64 = 125

    iou_loss_fused<<<nblocks, BLOCK>>>(iou_pred, mask, ind, box_pred, box_gt,
                                       M, HW, total, (float*)d_out, out_size);
}